// round 3
// baseline (speedup 1.0000x reference)
#include <cuda_runtime.h>

#define BATCH 4096
#define T_STEPS 50
#define HID 256
#define HSTR (T_STEPS * HID)   // row stride of out: 12800 floats

// ---------------- scratch (no allocations allowed) ----------------
__device__ float g_h1[BATCH * 512];
__device__ float g_h2[BATCH * 256];
__device__ float g_z [BATCH * 128];
__device__ float g_xp[BATCH * 1024];
__device__ float g_c [BATCH * 256];

// ---------------- helpers ----------------
__device__ __forceinline__ float sigmoidf_fast(float x) {
    return 1.0f / (1.0f + __expf(-x));
}
__device__ __forceinline__ float tanhf_fast(float x) {
    return 2.0f / (1.0f + __expf(-2.0f * x)) - 1.0f;
}
__device__ __forceinline__ unsigned long long pack2(float a, float b) {
    unsigned long long r;
    asm("mov.b64 %0, {%1, %2};" : "=l"(r) : "f"(a), "f"(b));
    return r;
}
__device__ __forceinline__ void unpack2(unsigned long long v, float& a, float& b) {
    asm("mov.b64 {%0, %1}, %2;" : "=f"(a), "=f"(b) : "l"(v));
}
// packed dual-fp32 FMA (Blackwell f32x2 pipe, 2x scalar FFMA throughput)
__device__ __forceinline__ void ffma2(unsigned long long& d,
                                      unsigned long long a,
                                      unsigned long long b) {
    asm("fma.rn.f32x2 %0, %1, %2, %3;" : "=l"(d) : "l"(a), "l"(b), "l"(d));
}

// ---------------- generic C = act(A @ W^T + bias [+bias2]) ----------------
// A: [M,K] row-major, W: [N,K] row-major. BM=BN=64, BK=16, 256 threads, 4x4 microtile.
__global__ void __launch_bounds__(256) gemm_bias_kernel(
    const float* __restrict__ A, const float* __restrict__ W,
    const float* __restrict__ bias, const float* __restrict__ bias2,
    float* __restrict__ C, int M, int N, int K, int relu)
{
    __shared__ __align__(16) float As[16][68];
    __shared__ __align__(16) float Ws[16][68];
    const int tid = threadIdx.x;
    const int bm = blockIdx.y << 6;
    const int bn = blockIdx.x << 6;
    const int lr = tid >> 2;          // 0..63
    const int lc = (tid & 3) << 2;    // 0,4,8,12
    const int m0 = (tid >> 4) << 2;   // 0..60
    const int n0 = (tid & 15) << 2;   // 0..60

    float acc[4][4] = {};

    for (int k0 = 0; k0 < K; k0 += 16) {
        float4 av = *(const float4*)(A + (size_t)(bm + lr) * K + k0 + lc);
        float4 wv = *(const float4*)(W + (size_t)(bn + lr) * K + k0 + lc);
        As[lc + 0][lr] = av.x; As[lc + 1][lr] = av.y;
        As[lc + 2][lr] = av.z; As[lc + 3][lr] = av.w;
        Ws[lc + 0][lr] = wv.x; Ws[lc + 1][lr] = wv.y;
        Ws[lc + 2][lr] = wv.z; Ws[lc + 3][lr] = wv.w;
        __syncthreads();
        #pragma unroll
        for (int k = 0; k < 16; k++) {
            float4 a4 = *(const float4*)&As[k][m0];
            float4 b4 = *(const float4*)&Ws[k][n0];
            float a[4] = {a4.x, a4.y, a4.z, a4.w};
            float b[4] = {b4.x, b4.y, b4.z, b4.w};
            #pragma unroll
            for (int i = 0; i < 4; i++)
                #pragma unroll
                for (int j = 0; j < 4; j++)
                    acc[i][j] = fmaf(a[i], b[j], acc[i][j]);
        }
        __syncthreads();
    }

    #pragma unroll
    for (int j = 0; j < 4; j++) {
        float bv = bias[bn + n0 + j];
        if (bias2) bv += bias2[bn + n0 + j];
        #pragma unroll
        for (int i = 0; i < 4; i++) {
            float v = acc[i][j] + bv;
            if (relu) v = fmaxf(v, 0.0f);
            C[(size_t)(bm + m0 + i) * N + (bn + n0 + j)] = v;
        }
    }
}

// ---------------- fused LSTM step ----------------
// Computes gates = x_part + h_{t-1} @ W_hh^T for a 64x32 tile of (batch, hidden),
// then the LSTM cell update, writing h_t directly into out[:, t, :].
// h_{t-1} is read from out[:, t-1, :]. Packed f32x2 accumulation over row pairs.
__global__ void __launch_bounds__(256) lstm_step_kernel(
    const float* __restrict__ xp,     // [B, 1024] precomputed input part
    const float* __restrict__ Whh,    // [1024, 256]
    float* __restrict__ out,          // [B, T, H]
    float* __restrict__ c,            // [B, H] cell state
    int t)
{
    __shared__ __align__(16) float hs[32][66];       // [k][row], padded
    __shared__ __align__(16) float ws[4][32][33];    // [gate][k][j], padded

    const int tid = threadIdx.x;
    const int tx = tid & 31;        // j within tile
    const int ty = tid >> 5;        // row-group (8 rows each)
    const int bm = blockIdx.y << 6; // batch tile base
    const int jb = blockIdx.x << 5; // hidden-col tile base

    unsigned long long acc[4][4];   // [row-pair][gate] packed f32x2
    #pragma unroll
    for (int p = 0; p < 4; p++)
        #pragma unroll
        for (int g = 0; g < 4; g++) acc[p][g] = 0ULL;

    if (t > 0) {
        const float* hprev = out + (size_t)(t - 1) * HID;
        const int wj = tid >> 3;             // 0..31
        const int wk = (tid & 7) << 2;       // 0,4,...,28
        for (int k0 = 0; k0 < HID; k0 += 32) {
            // h tile: 64 rows x 32 k
            #pragma unroll
            for (int q = 0; q < 2; q++) {
                int i4 = q * 256 + tid;
                int row = i4 >> 3;
                int kq = (i4 & 7) << 2;
                float4 v = *(const float4*)(hprev + (size_t)(bm + row) * HSTR + k0 + kq);
                hs[kq + 0][row] = v.x; hs[kq + 1][row] = v.y;
                hs[kq + 2][row] = v.z; hs[kq + 3][row] = v.w;
            }
            // W tiles: 4 gates x 32 j x 32 k
            #pragma unroll
            for (int g = 0; g < 4; g++) {
                float4 v = *(const float4*)(Whh + (size_t)(g * 256 + jb + wj) * HID + k0 + wk);
                ws[g][wk + 0][wj] = v.x; ws[g][wk + 1][wj] = v.y;
                ws[g][wk + 2][wj] = v.z; ws[g][wk + 3][wj] = v.w;
            }
            __syncthreads();
            #pragma unroll
            for (int k = 0; k < 32; k++) {
                unsigned long long w2[4], h2[4];
                #pragma unroll
                for (int g = 0; g < 4; g++) {
                    float wv = ws[g][k][tx];
                    w2[g] = pack2(wv, wv);
                }
                #pragma unroll
                for (int p = 0; p < 4; p++)
                    h2[p] = *(const unsigned long long*)&hs[k][ty * 8 + p * 2];
                #pragma unroll
                for (int p = 0; p < 4; p++)
                    #pragma unroll
                    for (int g = 0; g < 4; g++)
                        ffma2(acc[p][g], h2[p], w2[g]);
            }
            __syncthreads();
        }
    }

    // epilogue: LSTM cell
    const int col = jb + tx;
    #pragma unroll
    for (int p = 0; p < 4; p++) {
        float lo[4], hi[4];
        #pragma unroll
        for (int g = 0; g < 4; g++) unpack2(acc[p][g], lo[g], hi[g]);
        #pragma unroll
        for (int rr = 0; rr < 2; rr++) {
            const float* gv = rr ? hi : lo;
            const int row = bm + ty * 8 + p * 2 + rr;
            const size_t xb = (size_t)row * 1024 + col;
            float vi = sigmoidf_fast(gv[0] + xp[xb]);
            float vf = sigmoidf_fast(gv[1] + xp[xb + 256]);
            float vg = tanhf_fast  (gv[2] + xp[xb + 512]);
            float vo = sigmoidf_fast(gv[3] + xp[xb + 768]);
            float cp = (t == 0) ? 0.0f : c[(size_t)row * HID + col];
            float cn = vf * cp + vi * vg;
            c[(size_t)row * HID + col] = cn;
            out[(size_t)row * HSTR + (size_t)t * HID + col] = vo * tanhf_fast(cn);
        }
    }
}

// ---------------- launch ----------------
extern "C" void kernel_launch(void* const* d_in, const int* in_sizes, int n_in,
                              void* d_out, int out_size)
{
    const float* zs  = (const float*)d_in[0];
    const float* W1  = (const float*)d_in[1];
    const float* b1  = (const float*)d_in[2];
    const float* W2  = (const float*)d_in[3];
    const float* b2  = (const float*)d_in[4];
    const float* W3  = (const float*)d_in[5];
    const float* b3  = (const float*)d_in[6];
    const float* Wih = (const float*)d_in[7];
    const float* Whh = (const float*)d_in[8];
    const float* bih = (const float*)d_in[9];
    const float* bhh = (const float*)d_in[10];
    float* out = (float*)d_out;

    float *h1, *h2, *z, *xpv, *cv;
    cudaGetSymbolAddress((void**)&h1,  g_h1);
    cudaGetSymbolAddress((void**)&h2,  g_h2);
    cudaGetSymbolAddress((void**)&z,   g_z);
    cudaGetSymbolAddress((void**)&xpv, g_xp);
    cudaGetSymbolAddress((void**)&cv,  g_c);

    // MLP: h1 = relu(zs@W1^T+b1); h2 = relu(h1@W2^T+b2); z = h2@W3^T+b3
    gemm_bias_kernel<<<dim3(512 / 64,  BATCH / 64), 256>>>(zs, W1, b1, nullptr, h1, BATCH, 512, 256, 1);
    gemm_bias_kernel<<<dim3(256 / 64,  BATCH / 64), 256>>>(h1, W2, b2, nullptr, h2, BATCH, 256, 512, 1);
    gemm_bias_kernel<<<dim3(128 / 64,  BATCH / 64), 256>>>(h2, W3, b3, nullptr, z,  BATCH, 128, 256, 0);
    // x_part = z@W_ih^T + b_ih + b_hh
    gemm_bias_kernel<<<dim3(1024 / 64, BATCH / 64), 256>>>(z, Wih, bih, bhh, xpv, BATCH, 1024, 128, 0);

    // 50 fused LSTM steps
    for (int t = 0; t < T_STEPS; t++)
        lstm_step_kernel<<<dim3(HID / 32, BATCH / 64), 256>>>(xpv, Whh, out, cv, t);
}

// round 6
// speedup vs baseline: 1.6523x; 1.6523x over previous
#include <cuda_runtime.h>
#include <cstdint>

#define BATCH 4096
#define T_STEPS 50
#define HID 256
#define HSTR (T_STEPS * HID)   // out row stride: 12800 floats

// ---------------- scratch (no allocations allowed) ----------------
__device__ float g_h1[BATCH * 512];
__device__ float g_h2[BATCH * 256];
__device__ float g_z [BATCH * 128];
__device__ float g_xp[1024 * BATCH];   // TRANSPOSED: [1024][4096]
__device__ float g_c [256  * BATCH];   // TRANSPOSED: [256][4096]

// ---------------- helpers ----------------
__device__ __forceinline__ uint32_t f2tf(float x) {
    uint32_t r;
    asm("cvt.rna.tf32.f32 %0, %1;" : "=r"(r) : "f"(x));
    return r;
}
__device__ __forceinline__ void mma8(float* c, const uint32_t* a, const uint32_t* b) {
    asm volatile(
        "mma.sync.aligned.m16n8k8.row.col.f32.tf32.tf32.f32 "
        "{%0,%1,%2,%3}, {%4,%5,%6,%7}, {%8,%9}, {%0,%1,%2,%3};"
        : "+f"(c[0]), "+f"(c[1]), "+f"(c[2]), "+f"(c[3])
        : "r"(a[0]), "r"(a[1]), "r"(a[2]), "r"(a[3]), "r"(b[0]), "r"(b[1]));
}
__device__ __forceinline__ float sigmoidf_fast(float x) {
    return __fdividef(1.0f, 1.0f + __expf(-x));
}
__device__ __forceinline__ float tanhf_fast(float x) {
    return fmaf(2.0f, __fdividef(1.0f, 1.0f + __expf(-2.0f * x)), -1.0f);
}

// ---------------- generic C = act(A @ W^T + bias [+bias2]) ----------------
__global__ void __launch_bounds__(256) gemm_bias_kernel(
    const float* __restrict__ A, const float* __restrict__ W,
    const float* __restrict__ bias, const float* __restrict__ bias2,
    float* __restrict__ C, int M, int N, int K, int relu, int transC)
{
    __shared__ __align__(16) float As[16][68];
    __shared__ __align__(16) float Ws[16][68];
    const int tid = threadIdx.x;
    const int bm = blockIdx.y << 6;
    const int bn = blockIdx.x << 6;
    const int lr = tid >> 2;
    const int lc = (tid & 3) << 2;
    const int m0 = (tid >> 4) << 2;
    const int n0 = (tid & 15) << 2;

    float acc[4][4] = {};

    for (int k0 = 0; k0 < K; k0 += 16) {
        float4 av = *(const float4*)(A + (size_t)(bm + lr) * K + k0 + lc);
        float4 wv = *(const float4*)(W + (size_t)(bn + lr) * K + k0 + lc);
        As[lc + 0][lr] = av.x; As[lc + 1][lr] = av.y;
        As[lc + 2][lr] = av.z; As[lc + 3][lr] = av.w;
        Ws[lc + 0][lr] = wv.x; Ws[lc + 1][lr] = wv.y;
        Ws[lc + 2][lr] = wv.z; Ws[lc + 3][lr] = wv.w;
        __syncthreads();
        #pragma unroll
        for (int k = 0; k < 16; k++) {
            float4 a4 = *(const float4*)&As[k][m0];
            float4 b4 = *(const float4*)&Ws[k][n0];
            float a[4] = {a4.x, a4.y, a4.z, a4.w};
            float b[4] = {b4.x, b4.y, b4.z, b4.w};
            #pragma unroll
            for (int i = 0; i < 4; i++)
                #pragma unroll
                for (int j = 0; j < 4; j++)
                    acc[i][j] = fmaf(a[i], b[j], acc[i][j]);
        }
        __syncthreads();
    }

    #pragma unroll
    for (int j = 0; j < 4; j++) {
        float bv = bias[bn + n0 + j];
        if (bias2) bv += bias2[bn + n0 + j];
        #pragma unroll
        for (int i = 0; i < 4; i++) {
            float v = acc[i][j] + bv;
            if (relu) v = fmaxf(v, 0.0f);
            if (transC)
                C[(size_t)(bn + n0 + j) * M + (bm + m0 + i)] = v;
            else
                C[(size_t)(bm + m0 + i) * N + (bn + n0 + j)] = v;
        }
    }
}

// ---------------- tf32 mma.sync LSTM step ----------------
// CTA: 256 threads (8 warps), D tile = [128 batch][128 cols], col n = g*32 + j
// (gate-interleaved). Warp tile 32x64: warps laid out 4(M) x 2(N).
// K = 256 in 8 chunks of 32, double-buffered LDG->cvt(tf32,rna)->STS staging.
// PTX m16n8k8 tf32 fragment mapping (two stacked k4 ops):
//   a0=(r,q) a1=(r+8,q) a2=(r,q+4) a3=(r+8,q+4); b0=(q,c) b1=(q+4,c)
//   with q=lane&3, r/c = lane>>2. Stride 36 (mod 32 = 4) -> bank = 4r+q,
//   conflict-free scalar LDS for fragments.

#define SM_STRIDE 36                       // uint32 stride per staged row
#define SM_A0 0
#define SM_A1 (128 * SM_STRIDE * 4)        // 18432
#define SM_B0 (2 * 128 * SM_STRIDE * 4)
#define SM_B1 (3 * 128 * SM_STRIDE * 4)
#define SM_HS (4 * 128 * SM_STRIDE * 4)    // 73728 (h staging, 128x33 f32)
#define SMEM_REQ (SM_HS + 128 * 33 * 4)    // 90624
#define GS_STRIDE 133                      // gate buffer stride (aliases A0..B1)

__global__ void __launch_bounds__(256, 2)
lstm_step_mma(const float* __restrict__ xpt,   // [1024][4096] transposed
              const float* __restrict__ Whh,   // [1024][256]
              float* __restrict__ out,         // [B][T][H]
              float* __restrict__ ct,          // [256][4096] transposed
              int t)
{
    extern __shared__ char sm[];
    const int tid  = threadIdx.x;
    const int wid  = tid >> 5;
    const int lane = tid & 31;
    const int wm   = wid & 3;       // warp M index (0..3)
    const int wn   = wid >> 2;      // warp N index (0..1)
    const int bm   = blockIdx.y * 128;
    const int jb   = blockIdx.x * 32;

    float acc[2][8][4];
    #pragma unroll
    for (int mi = 0; mi < 2; mi++)
        #pragma unroll
        for (int ni = 0; ni < 8; ni++)
            #pragma unroll
            for (int v = 0; v < 4; v++) acc[mi][ni][v] = 0.0f;

    if (t > 0) {
        const float* hbase = out + (size_t)(t - 1) * HID;
        const int srow = tid >> 3;          // staged row (+i*32)
        const int sk4  = (tid & 7) << 2;    // float4 col offset in k
        float4 ra[4], rb[4];

        // prologue: LDG chunk 0, STS buf0
        #pragma unroll
        for (int i = 0; i < 4; i++) {
            int row = i * 32 + srow;
            ra[i] = *(const float4*)(hbase + (size_t)(bm + row) * HSTR + sk4);
            int wrow = ((row >> 5) << 8) + jb + (row & 31);
            rb[i] = *(const float4*)(Whh + (size_t)wrow * HID + sk4);
        }
        #pragma unroll
        for (int i = 0; i < 4; i++) {
            int row = i * 32 + srow;
            uint4 ua = { f2tf(ra[i].x), f2tf(ra[i].y), f2tf(ra[i].z), f2tf(ra[i].w) };
            uint4 ub = { f2tf(rb[i].x), f2tf(rb[i].y), f2tf(rb[i].z), f2tf(rb[i].w) };
            *(uint4*)(sm + SM_A0 + (row * SM_STRIDE + sk4) * 4) = ua;
            *(uint4*)(sm + SM_B0 + (row * SM_STRIDE + sk4) * 4) = ub;
        }
        __syncthreads();

        const int ar = wm * 32 + (lane >> 2);   // A fragment base row
        const int bc = wn * 64 + (lane >> 2);   // B fragment base col
        const int q  = lane & 3;                // fragment k index

        #pragma unroll 1
        for (int ch = 0; ch < 8; ch++) {
            // prefetch next chunk into regs (LDG overlaps MMA)
            if (ch < 7) {
                const int k0 = (ch + 1) * 32;
                #pragma unroll
                for (int i = 0; i < 4; i++) {
                    int row = i * 32 + srow;
                    ra[i] = *(const float4*)(hbase + (size_t)(bm + row) * HSTR + k0 + sk4);
                    int wrow = ((row >> 5) << 8) + jb + (row & 31);
                    rb[i] = *(const float4*)(Whh + (size_t)wrow * HID + k0 + sk4);
                }
            }
            // compute current chunk
            const uint32_t* As = (const uint32_t*)(sm + ((ch & 1) ? SM_A1 : SM_A0));
            const uint32_t* Bs = (const uint32_t*)(sm + ((ch & 1) ? SM_B1 : SM_B0));
            #pragma unroll
            for (int kk = 0; kk < 4; kk++) {
                const int kb = kk * 8 + q;
                uint32_t a[2][4], b[8][2];
                #pragma unroll
                for (int mi = 0; mi < 2; mi++) {
                    const int r0 = (ar + mi * 16) * SM_STRIDE;
                    const int r8 = (ar + mi * 16 + 8) * SM_STRIDE;
                    a[mi][0] = As[r0 + kb];
                    a[mi][1] = As[r8 + kb];
                    a[mi][2] = As[r0 + kb + 4];
                    a[mi][3] = As[r8 + kb + 4];
                }
                #pragma unroll
                for (int ni = 0; ni < 8; ni++) {
                    const int rB = (bc + ni * 8) * SM_STRIDE;
                    b[ni][0] = Bs[rB + kb];
                    b[ni][1] = Bs[rB + kb + 4];
                }
                #pragma unroll
                for (int mi = 0; mi < 2; mi++)
                    #pragma unroll
                    for (int ni = 0; ni < 8; ni++)
                        mma8(acc[mi][ni], a[mi], b[ni]);
            }
            __syncthreads();
            if (ch < 7) {
                char* da = sm + (((ch + 1) & 1) ? SM_A1 : SM_A0);
                char* db = sm + (((ch + 1) & 1) ? SM_B1 : SM_B0);
                #pragma unroll
                for (int i = 0; i < 4; i++) {
                    int row = i * 32 + srow;
                    uint4 ua = { f2tf(ra[i].x), f2tf(ra[i].y), f2tf(ra[i].z), f2tf(ra[i].w) };
                    uint4 ub = { f2tf(rb[i].x), f2tf(rb[i].y), f2tf(rb[i].z), f2tf(rb[i].w) };
                    *(uint4*)(da + (row * SM_STRIDE + sk4) * 4) = ua;
                    *(uint4*)(db + (row * SM_STRIDE + sk4) * 4) = ub;
                }
                __syncthreads();
            }
        }

        // store accumulators into gate buffer (aliases staging; all compute done)
        float* gs = (float*)sm;
        const int grow = wm * 32 + (lane >> 2);
        const int gcol = wn * 64 + ((lane & 3) << 1);
        #pragma unroll
        for (int mi = 0; mi < 2; mi++)
            #pragma unroll
            for (int ni = 0; ni < 8; ni++) {
                int r = grow + mi * 16, cc = gcol + ni * 8;
                gs[r * GS_STRIDE + cc]           = acc[mi][ni][0];
                gs[r * GS_STRIDE + cc + 1]       = acc[mi][ni][1];
                gs[(r + 8) * GS_STRIDE + cc]     = acc[mi][ni][2];
                gs[(r + 8) * GS_STRIDE + cc + 1] = acc[mi][ni][3];
            }
        __syncthreads();
    }

    // ---------------- LSTM cell epilogue ----------------
    const float* gs = (const float*)sm;
    float* hsm = (float*)(sm + SM_HS);
    const int rloc = tid & 127;
    const int half = tid >> 7;
    const int brow = bm + rloc;

    #pragma unroll
    for (int i = 0; i < 16; i++) {
        const int j = i * 2 + half;
        float gi, gf, gg, go, cp;
        if (t > 0) {
            gi = gs[rloc * GS_STRIDE + j];
            gf = gs[rloc * GS_STRIDE + 32 + j];
            gg = gs[rloc * GS_STRIDE + 64 + j];
            go = gs[rloc * GS_STRIDE + 96 + j];
            cp = ct[(size_t)(jb + j) * BATCH + brow];
        } else {
            gi = gf = gg = go = 0.0f; cp = 0.0f;
        }
        gi += xpt[(size_t)(      jb + j) * BATCH + brow];
        gf += xpt[(size_t)(256 + jb + j) * BATCH + brow];
        gg += xpt[(size_t)(512 + jb + j) * BATCH + brow];
        go += xpt[(size_t)(768 + jb + j) * BATCH + brow];
        float vi = sigmoidf_fast(gi);
        float vf = sigmoidf_fast(gf);
        float vg = tanhf_fast(gg);
        float vo = sigmoidf_fast(go);
        float cn = vf * cp + vi * vg;
        ct[(size_t)(jb + j) * BATCH + brow] = cn;
        hsm[rloc * 33 + j] = vo * tanhf_fast(cn);
    }
    __syncthreads();

    // coalesced h write: each warp writes one 128B row segment per iteration
    #pragma unroll
    for (int i = 0; i < 16; i++) {
        int row = i * 8 + wid;
        out[(size_t)(bm + row) * HSTR + (size_t)t * HID + jb + lane] = hsm[row * 33 + lane];
    }
}

// ---------------- launch ----------------
extern "C" void kernel_launch(void* const* d_in, const int* in_sizes, int n_in,
                              void* d_out, int out_size)
{
    const float* zs  = (const float*)d_in[0];
    const float* W1  = (const float*)d_in[1];
    const float* b1  = (const float*)d_in[2];
    const float* W2  = (const float*)d_in[3];
    const float* b2  = (const float*)d_in[4];
    const float* W3  = (const float*)d_in[5];
    const float* b3  = (const float*)d_in[6];
    const float* Wih = (const float*)d_in[7];
    const float* Whh = (const float*)d_in[8];
    const float* bih = (const float*)d_in[9];
    const float* bhh = (const float*)d_in[10];
    float* out = (float*)d_out;

    float *h1, *h2, *z, *xpv, *cv;
    cudaGetSymbolAddress((void**)&h1,  g_h1);
    cudaGetSymbolAddress((void**)&h2,  g_h2);
    cudaGetSymbolAddress((void**)&z,   g_z);
    cudaGetSymbolAddress((void**)&xpv, g_xp);
    cudaGetSymbolAddress((void**)&cv,  g_c);

    cudaFuncSetAttribute(lstm_step_mma,
                         cudaFuncAttributeMaxDynamicSharedMemorySize, SMEM_REQ);

    // MLP
    gemm_bias_kernel<<<dim3(512 / 64,  BATCH / 64), 256>>>(zs, W1, b1, nullptr, h1, BATCH, 512, 256, 1, 0);
    gemm_bias_kernel<<<dim3(256 / 64,  BATCH / 64), 256>>>(h1, W2, b2, nullptr, h2, BATCH, 256, 512, 1, 0);
    gemm_bias_kernel<<<dim3(128 / 64,  BATCH / 64), 256>>>(h2, W3, b3, nullptr, z,  BATCH, 128, 256, 0, 0);
    // x_part TRANSPOSED: xpt[n][m] = (z @ Wih^T + bih + bhh)[m][n]
    gemm_bias_kernel<<<dim3(1024 / 64, BATCH / 64), 256>>>(z, Wih, bih, bhh, xpv, BATCH, 1024, 128, 0, 1);

    // 50 tensor-core LSTM steps
    for (int t = 0; t < T_STEPS; t++)
        lstm_step_mma<<<dim3(HID / 32, BATCH / 128), 256, SMEM_REQ>>>(xpv, Whh, out, cv, t);
}

// round 7
// speedup vs baseline: 2.8460x; 1.7225x over previous
#include <cuda_runtime.h>
#include <cstdint>

#define BATCH 4096
#define T_STEPS 50
#define HID 256
#define HSTR (T_STEPS * HID)   // out row stride: 12800 floats

// ---------------- scratch (no allocations allowed) ----------------
__device__ float g_zs_tf[BATCH * 256];
__device__ float g_w1 [512 * 256];
__device__ float g_w2 [256 * 512];
__device__ float g_w3 [128 * 256];
__device__ float g_wih[1024 * 128];
__device__ float g_whhc[1024 * 256];   // permuted: row' = jb8*128 + g*32 + j
__device__ float g_h1[BATCH * 512];    // tf32
__device__ float g_h2[BATCH * 256];    // tf32
__device__ float g_z [BATCH * 128];    // tf32
__device__ float g_xp[1024 * BATCH];   // fp32 TRANSPOSED: [1024][4096]
__device__ float g_c [256  * BATCH];   // fp32 TRANSPOSED: [256][4096]
__device__ float g_ht[BATCH * 256];    // tf32 compact h_{t-1}

// ---------------- helpers ----------------
__device__ __forceinline__ uint32_t f2tf(float x) {
    uint32_t r;
    asm("cvt.rna.tf32.f32 %0, %1;" : "=r"(r) : "f"(x));
    return r;
}
__device__ __forceinline__ float f2tf_f(float x) { return __uint_as_float(f2tf(x)); }
__device__ __forceinline__ uint32_t smem_u32(const void* p) {
    uint32_t a;
    asm("{ .reg .u64 t; cvta.to.shared.u64 t, %1; cvt.u32.u64 %0, t; }" : "=r"(a) : "l"(p));
    return a;
}
__device__ __forceinline__ void cp16(uint32_t d, const void* s) {
    asm volatile("cp.async.cg.shared.global [%0], [%1], 16;" :: "r"(d), "l"(s));
}
__device__ __forceinline__ void cp_commit() {
    asm volatile("cp.async.commit_group;");
}
__device__ __forceinline__ void cp_wait1() {
    asm volatile("cp.async.wait_group 1;" ::: "memory");
}
__device__ __forceinline__ void cp_wait0() {
    asm volatile("cp.async.wait_group 0;" ::: "memory");
}
__device__ __forceinline__ void mma8(float* c, const uint32_t* a, const uint32_t* b) {
    asm volatile(
        "mma.sync.aligned.m16n8k8.row.col.f32.tf32.tf32.f32 "
        "{%0,%1,%2,%3}, {%4,%5,%6,%7}, {%8,%9}, {%0,%1,%2,%3};"
        : "+f"(c[0]), "+f"(c[1]), "+f"(c[2]), "+f"(c[3])
        : "r"(a[0]), "r"(a[1]), "r"(a[2]), "r"(a[3]), "r"(b[0]), "r"(b[1]));
}
__device__ __forceinline__ float sigmoidf_fast(float x) {
    return __fdividef(1.0f, 1.0f + __expf(-x));
}
__device__ __forceinline__ float tanhf_fast(float x) {
    return fmaf(2.0f, __fdividef(1.0f, 1.0f + __expf(-2.0f * x)), -1.0f);
}

// ---------------- conversion kernels ----------------
__global__ void conv_tf_kernel(const float* __restrict__ src, float* __restrict__ dst, int n) {
    int i = blockIdx.x * 256 + threadIdx.x;
    if (i < n) dst[i] = f2tf_f(src[i]);
}
__global__ void conv_whh_kernel(const float* __restrict__ whh, float* __restrict__ dst) {
    // dst[(jb8*128 + g*32 + j)][k] = tf(whh[(g*256 + jb8*32 + j)][k])
    int k = threadIdx.x;          // 0..255
    int r = blockIdx.x;           // 0..1023
    int jb8 = r >> 7, g = (r >> 5) & 3, j = r & 31;
    dst[r * 256 + k] = f2tf_f(whh[(size_t)(g * 256 + jb8 * 32 + j) * 256 + k]);
}

// ---------------- shared tile geometry ----------------
#define SM_STRIDE 36                              // uint32 stride per staged row
#define HALF_STAGE (128 * SM_STRIDE * 4)          // 18432 (A half)
#define STAGE_BYTES (2 * HALF_STAGE)              // 36864 (A + B)
#define GEMM_SMEM (3 * STAGE_BYTES)               // 110592, 3 stages
#define GS_STRIDE 133                             // gate/output stage stride
#define HS_OFF (128 * GS_STRIDE * 4)              // hsm after gs (68096)

// ---- shared mainloop: 3-stage cp.async pipelined tf32 mma ----
// A rows at stage+0, B rows at stage+HALF_STAGE; both [128 rows][K-chunk 32].
// Fragment map (PTX m16n8k8 tf32): q=lane&3, r=lane>>2;
//   a0=(r,q) a1=(r+8,q) a2=(r,q+4) a3=(r+8,q+4); b0=(q,c) b1=(q+4,c)

__device__ __forceinline__ void mma_mainloop(
    char* sm, const float* __restrict__ A, const float* __restrict__ B,
    int aRowBase, int bRowBase, int K, int tid, float acc[2][8][4])
{
    const int srow = tid >> 3;            // 0..31
    const int sk4  = (tid & 7) << 2;      // 0..28
    const int lane = tid & 31;
    const int wid  = tid >> 5;
    const int wm   = wid & 3, wn = wid >> 2;
    const int ar = wm * 32 + (lane >> 2);
    const int bc = wn * 64 + (lane >> 2);
    const int q  = lane & 3;
    const int NC = K >> 5;

    // prologue: issue stages 0,1
    #pragma unroll
    for (int st = 0; st < 2; st++) {
        uint32_t da = smem_u32(sm + st * STAGE_BYTES);
        uint32_t db = da + HALF_STAGE;
        const int k0 = st * 32;
        #pragma unroll
        for (int i = 0; i < 4; i++) {
            int row = i * 32 + srow;
            cp16(da + (uint32_t)(row * SM_STRIDE + sk4) * 4,
                 A + (size_t)(aRowBase + row) * K + k0 + sk4);
            cp16(db + (uint32_t)(row * SM_STRIDE + sk4) * 4,
                 B + (size_t)(bRowBase + row) * K + k0 + sk4);
        }
        cp_commit();
    }

    #pragma unroll 1
    for (int ch = 0; ch < NC; ch++) {
        if (ch == NC - 1) cp_wait0(); else cp_wait1();
        __syncthreads();
        const uint32_t* As = (const uint32_t*)(sm + (ch % 3) * STAGE_BYTES);
        const uint32_t* Bs = As + HALF_STAGE / 4;
        #pragma unroll
        for (int kk = 0; kk < 4; kk++) {
            const int kb = kk * 8 + q;
            uint32_t a[2][4], b[8][2];
            #pragma unroll
            for (int mi = 0; mi < 2; mi++) {
                const int r0 = (ar + mi * 16) * SM_STRIDE;
                const int r8 = (ar + mi * 16 + 8) * SM_STRIDE;
                a[mi][0] = As[r0 + kb];
                a[mi][1] = As[r8 + kb];
                a[mi][2] = As[r0 + kb + 4];
                a[mi][3] = As[r8 + kb + 4];
            }
            #pragma unroll
            for (int ni = 0; ni < 8; ni++) {
                const int rB = (bc + ni * 8) * SM_STRIDE;
                b[ni][0] = Bs[rB + kb];
                b[ni][1] = Bs[rB + kb + 4];
            }
            #pragma unroll
            for (int mi = 0; mi < 2; mi++)
                #pragma unroll
                for (int ni = 0; ni < 8; ni++)
                    mma8(acc[mi][ni], a[mi], b[ni]);
        }
        __syncthreads();
        if (ch + 2 < NC) {
            const int st = ch + 2;
            uint32_t da = smem_u32(sm + (st % 3) * STAGE_BYTES);
            uint32_t db = da + HALF_STAGE;
            const int k0 = st * 32;
            #pragma unroll
            for (int i = 0; i < 4; i++) {
                int row = i * 32 + srow;
                cp16(da + (uint32_t)(row * SM_STRIDE + sk4) * 4,
                     A + (size_t)(aRowBase + row) * K + k0 + sk4);
                cp16(db + (uint32_t)(row * SM_STRIDE + sk4) * 4,
                     B + (size_t)(bRowBase + row) * K + k0 + sk4);
            }
            cp_commit();
        }
    }
}

// store accumulators to smem gate/output buffer gs[128][GS_STRIDE]
__device__ __forceinline__ void stage_acc(char* sm, int tid, float acc[2][8][4]) {
    float* gs = (float*)sm;
    const int lane = tid & 31, wid = tid >> 5;
    const int wm = wid & 3, wn = wid >> 2;
    const int grow = wm * 32 + (lane >> 2);
    const int gcol = wn * 64 + ((lane & 3) << 1);
    #pragma unroll
    for (int mi = 0; mi < 2; mi++)
        #pragma unroll
        for (int ni = 0; ni < 8; ni++) {
            int r = grow + mi * 16, cc = gcol + ni * 8;
            gs[r * GS_STRIDE + cc]           = acc[mi][ni][0];
            gs[r * GS_STRIDE + cc + 1]       = acc[mi][ni][1];
            gs[(r + 8) * GS_STRIDE + cc]     = acc[mi][ni][2];
            gs[(r + 8) * GS_STRIDE + cc + 1] = acc[mi][ni][3];
        }
}

// ---------------- generic tf32 mma GEMM (MLP layers) ----------------
// C = act(A[M,K] @ B[N,K]^T + bias [+bias2]); A,B already tf32.
__global__ void __launch_bounds__(256, 2) mma_gemm(
    const float* __restrict__ A, const float* __restrict__ B,
    const float* __restrict__ bias, const float* __restrict__ bias2,
    float* __restrict__ C, int M, int N, int K,
    int relu, int transC, int out_tf)
{
    extern __shared__ char sm[];
    const int tid = threadIdx.x;
    const int wid = tid >> 5, lane = tid & 31;
    const int bm = blockIdx.y * 128, bn = blockIdx.x * 128;

    float acc[2][8][4];
    #pragma unroll
    for (int mi = 0; mi < 2; mi++)
        #pragma unroll
        for (int ni = 0; ni < 8; ni++)
            #pragma unroll
            for (int v = 0; v < 4; v++) acc[mi][ni][v] = 0.0f;

    mma_mainloop(sm, A, B, bm, bn, K, tid, acc);
    stage_acc(sm, tid, acc);
    __syncthreads();

    const float* gs = (const float*)sm;
    if (!transC) {
        #pragma unroll
        for (int i = 0; i < 16; i++) {
            int row = i * 8 + wid;
            #pragma unroll
            for (int cc = 0; cc < 4; cc++) {
                int col = cc * 32 + lane;
                float bv = bias[bn + col];
                if (bias2) bv += bias2[bn + col];
                float v = gs[row * GS_STRIDE + col] + bv;
                if (relu) v = fmaxf(v, 0.0f);
                if (out_tf) v = f2tf_f(v);
                C[(size_t)(bm + row) * N + bn + col] = v;
            }
        }
    } else {
        #pragma unroll
        for (int i = 0; i < 16; i++) {
            int col = i * 8 + wid;
            float bv = bias[bn + col];
            if (bias2) bv += bias2[bn + col];
            #pragma unroll
            for (int cc = 0; cc < 4; cc++) {
                int row = cc * 32 + lane;
                float v = gs[row * GS_STRIDE + col] + bv;
                if (relu) v = fmaxf(v, 0.0f);
                if (out_tf) v = f2tf_f(v);
                C[(size_t)(bn + col) * M + bm + row] = v;
            }
        }
    }
}

// ---------------- tf32 mma LSTM step ----------------
// D tile [128 batch][128 cols], col n = g*32 + j (gate-interleaved via g_whhc).
__global__ void __launch_bounds__(256, 2)
lstm_step_mma(const float* __restrict__ ht,     // [4096][256] tf32 compact h_{t-1}
              const float* __restrict__ whhc,   // [1024][256] tf32 permuted
              const float* __restrict__ xpt,    // [1024][4096] fp32 transposed
              float* __restrict__ out,          // [B][T][H]
              float* __restrict__ ct,           // [256][4096] fp32 transposed
              float* __restrict__ htn,          // [4096][256] tf32 h_t (written)
              int t)
{
    extern __shared__ char sm[];
    const int tid  = threadIdx.x;
    const int wid  = tid >> 5;
    const int lane = tid & 31;
    const int bm   = blockIdx.y * 128;
    const int jb   = blockIdx.x * 32;

    float acc[2][8][4];
    #pragma unroll
    for (int mi = 0; mi < 2; mi++)
        #pragma unroll
        for (int ni = 0; ni < 8; ni++)
            #pragma unroll
            for (int v = 0; v < 4; v++) acc[mi][ni][v] = 0.0f;

    if (t > 0) {
        mma_mainloop(sm, ht, whhc, bm, (int)blockIdx.x * 128, HID, tid, acc);
        stage_acc(sm, tid, acc);
        __syncthreads();
    }

    // ---------------- LSTM cell epilogue ----------------
    const float* gs = (const float*)sm;
    float* hsm = (float*)(sm + HS_OFF);
    const int rloc = tid & 127;
    const int half = tid >> 7;
    const int brow = bm + rloc;

    #pragma unroll
    for (int i = 0; i < 16; i++) {
        const int j = i * 2 + half;
        float gi, gf, gg, go, cp;
        if (t > 0) {
            gi = gs[rloc * GS_STRIDE + j];
            gf = gs[rloc * GS_STRIDE + 32 + j];
            gg = gs[rloc * GS_STRIDE + 64 + j];
            go = gs[rloc * GS_STRIDE + 96 + j];
            cp = ct[(size_t)(jb + j) * BATCH + brow];
        } else {
            gi = gf = gg = go = 0.0f; cp = 0.0f;
        }
        gi += xpt[(size_t)(      jb + j) * BATCH + brow];
        gf += xpt[(size_t)(256 + jb + j) * BATCH + brow];
        gg += xpt[(size_t)(512 + jb + j) * BATCH + brow];
        go += xpt[(size_t)(768 + jb + j) * BATCH + brow];
        float vi = sigmoidf_fast(gi);
        float vf = sigmoidf_fast(gf);
        float vg = tanhf_fast(gg);
        float vo = sigmoidf_fast(go);
        float cn = vf * cp + vi * vg;
        ct[(size_t)(jb + j) * BATCH + brow] = cn;
        hsm[rloc * 33 + j] = vo * tanhf_fast(cn);
    }
    __syncthreads();

    // coalesced writes: out (fp32) and htn (tf32 compact)
    #pragma unroll
    for (int i = 0; i < 16; i++) {
        int row = i * 8 + wid;
        float v = hsm[row * 33 + lane];
        out[(size_t)(bm + row) * HSTR + (size_t)t * HID + jb + lane] = v;
        htn[(size_t)(bm + row) * HID + jb + lane] = f2tf_f(v);
    }
}

// ---------------- launch ----------------
extern "C" void kernel_launch(void* const* d_in, const int* in_sizes, int n_in,
                              void* d_out, int out_size)
{
    const float* zs  = (const float*)d_in[0];
    const float* W1  = (const float*)d_in[1];
    const float* b1  = (const float*)d_in[2];
    const float* W2  = (const float*)d_in[3];
    const float* b2  = (const float*)d_in[4];
    const float* W3  = (const float*)d_in[5];
    const float* b3  = (const float*)d_in[6];
    const float* Wih = (const float*)d_in[7];
    const float* Whh = (const float*)d_in[8];
    const float* bih = (const float*)d_in[9];
    const float* bhh = (const float*)d_in[10];
    float* out = (float*)d_out;

    float *zs_tf, *w1, *w2, *w3, *wih, *whhc, *h1, *h2, *z, *xp, *cv, *ht;
    cudaGetSymbolAddress((void**)&zs_tf, g_zs_tf);
    cudaGetSymbolAddress((void**)&w1,   g_w1);
    cudaGetSymbolAddress((void**)&w2,   g_w2);
    cudaGetSymbolAddress((void**)&w3,   g_w3);
    cudaGetSymbolAddress((void**)&wih,  g_wih);
    cudaGetSymbolAddress((void**)&whhc, g_whhc);
    cudaGetSymbolAddress((void**)&h1,   g_h1);
    cudaGetSymbolAddress((void**)&h2,   g_h2);
    cudaGetSymbolAddress((void**)&z,    g_z);
    cudaGetSymbolAddress((void**)&xp,   g_xp);
    cudaGetSymbolAddress((void**)&cv,   g_c);
    cudaGetSymbolAddress((void**)&ht,   g_ht);

    cudaFuncSetAttribute(mma_gemm,
                         cudaFuncAttributeMaxDynamicSharedMemorySize, GEMM_SMEM);
    cudaFuncSetAttribute(lstm_step_mma,
                         cudaFuncAttributeMaxDynamicSharedMemorySize, GEMM_SMEM);

    // one-time conversions (inside graph; deterministic)
    conv_tf_kernel<<<(BATCH * 256 + 255) / 256, 256>>>(zs, zs_tf, BATCH * 256);
    conv_tf_kernel<<<(512 * 256 + 255) / 256, 256>>>(W1, w1, 512 * 256);
    conv_tf_kernel<<<(256 * 512 + 255) / 256, 256>>>(W2, w2, 256 * 512);
    conv_tf_kernel<<<(128 * 256 + 255) / 256, 256>>>(W3, w3, 128 * 256);
    conv_tf_kernel<<<(1024 * 128 + 255) / 256, 256>>>(Wih, wih, 1024 * 128);
    conv_whh_kernel<<<1024, 256>>>(Whh, whhc);

    // MLP (tf32 mma)
    mma_gemm<<<dim3(4, 32), 256, GEMM_SMEM>>>(zs_tf, w1, b1, nullptr, h1,
                                              BATCH, 512, 256, 1, 0, 1);
    mma_gemm<<<dim3(2, 32), 256, GEMM_SMEM>>>(h1, w2, b2, nullptr, h2,
                                              BATCH, 256, 512, 1, 0, 1);
    mma_gemm<<<dim3(1, 32), 256, GEMM_SMEM>>>(h2, w3, b3, nullptr, z,
                                              BATCH, 128, 256, 0, 0, 1);
    // x_part transposed fp32: xp[n][m]
    mma_gemm<<<dim3(8, 32), 256, GEMM_SMEM>>>(z, wih, bih, bhh, xp,
                                              BATCH, 1024, 128, 0, 1, 0);

    // 50 tensor-core LSTM steps
    for (int t = 0; t < T_STEPS; t++)
        lstm_step_mma<<<dim3(HID / 32, BATCH / 128), 256, GEMM_SMEM>>>(
            ht, whhc, xp, out, cv, ht, t);
}